// round 5
// baseline (speedup 1.0000x reference)
#include <cuda_runtime.h>
#include <cuda_fp16.h>
#include <cstdint>

// ---------------------------------------------------------------------------
// DARTSLayer as one fp16 tensor-core GEMM (mma.sync.m16n8k16):
//   out[b,j] = sum_{p,i} W[p*64+i, j] * prim_p(x[b,i])
// Round 3 -> 4: q-outer loop (xd live regs 64 -> 16), 256-thread CTAs,
// __launch_bounds__(256,2) for 2 CTAs/SM (occupancy 11% -> 25%).
// ---------------------------------------------------------------------------

#define BATCH   65536
#define NIN     64
#define NOUT    64
#define NKK     28              // K=448 / 16 per mma
#define WFRAG_N (NKK * 8 * 32)  // kk * ntile * lane -> uint2 (b0,b1)
#define SMEM_B  (WFRAG_N * 8)   // 57344 bytes

__device__ uint2 g_Wfrag[WFRAG_N];

// --------------------------- helpers ----------------------------------------

__device__ __forceinline__ uint32_t pack2(float lo, float hi) {
    uint32_t r;
    asm("cvt.rn.f16x2.f32 %0, %1, %2;" : "=r"(r) : "f"(hi), "f"(lo));
    return r;
}

__device__ __forceinline__ float frcp(float x) {
    float r;
    asm("rcp.approx.f32 %0, %1;" : "=f"(r) : "f"(x));
    return r;
}

__device__ __forceinline__ void mma16816(float* d, const uint32_t* a, uint2 b) {
    asm volatile(
        "mma.sync.aligned.m16n8k16.row.col.f32.f16.f16.f32 "
        "{%0,%1,%2,%3}, {%4,%5,%6,%7}, {%8,%9}, {%0,%1,%2,%3};"
        : "+f"(d[0]), "+f"(d[1]), "+f"(d[2]), "+f"(d[3])
        : "r"(a[0]), "r"(a[1]), "r"(a[2]), "r"(a[3]), "r"(b.x), "r"(b.y));
}

__device__ __forceinline__ float prim_eval(int p, float x) {
    switch (p) {
        case 0:  return x;            // linear
        case 1:  return x * x;        // power_two
        case 2:  return x * x * x;    // power_three
        case 3:  return __expf(x);    // exp
        case 4:  return __logf(x);    // ln
        case 5:  return frcp(x);      // reciprocal
        default: return __sinf(x);    // sin
    }
}

// --------------------------- W preparation -----------------------------------
// One thread per (i, j). Computes softmax-gated weights and scatters them as
// fp16 halves directly into the mma B-fragment layout:
//   frag element = ((kk*8 + nt)*32 + lane) -> uint2 {b0, b1}
//   b0 halves: k = 2c, 2c+1 ; b1 halves: k = 2c+8, 2c+9 ; n = lane/4 ; c = lane%4

__global__ void darts_prep_kernel(const float* __restrict__ alphas,
                                  const float* __restrict__ coeffs) {
    int idx = blockIdx.x * blockDim.x + threadIdx.x;  // i*64 + j
    if (idx >= NIN * NOUT) return;
    int i = idx >> 6;
    int j = idx & 63;

    float a[8];
#pragma unroll
    for (int k = 0; k < 8; k++) a[k] = alphas[idx * 8 + k];
    float m = a[0];
#pragma unroll
    for (int k = 1; k < 8; k++) m = fmaxf(m, a[k]);
    float e[8], s = 0.0f;
#pragma unroll
    for (int k = 0; k < 8; k++) { e[k] = __expf(a[k] - m); s += e[k]; }
    float inv = 1.0f / s;

    __half* dst = (__half*)g_Wfrag;
#pragma unroll
    for (int p = 0; p < 7; p++) {
        float wv = e[p + 1] * inv * coeffs[idx * 8 + p + 1];
        int k    = p * 64 + i;
        int kk   = k >> 4;
        int kpos = k & 15;
        int nt   = j >> 3;
        int lane = (j & 7) * 4 + ((kpos & 7) >> 1);
        int reg  = kpos >> 3;
        int half = kpos & 1;
        dst[(((kk * 8 + nt) * 32 + lane) * 2 + reg) * 2 + half] = __float2half_rn(wv);
    }
}

// --------------------------- main GEMM ---------------------------------------
// 256 threads (8 warps). Each warp: 32 batch rows x all 64 outputs x K=448.
// q (i-quarter) outer so only one q's x values (16 regs) are live at a time.
// grid = 256 CTAs (256-row tile each), 2 CTAs/SM.

__global__ void __launch_bounds__(256, 2)
darts_main_kernel(const float* __restrict__ x, float* __restrict__ out) {
    extern __shared__ uint2 sW[];
    int tid  = threadIdx.x;
    int wid  = tid >> 5;
    int lane = tid & 31;
    int r    = lane >> 2;   // 0..7
    int c    = lane & 3;    // 0..3

    // Stage W fragments into SMEM (coalesced uint4 copy, 57344 B)
    {
        const uint4* src = (const uint4*)g_Wfrag;
        uint4* dst = (uint4*)sW;
        for (int u = tid; u < WFRAG_N / 2; u += 256) dst[u] = src[u];
    }

    int warp_row0 = blockIdx.x * 256 + wid * 32;

    float acc[2][8][4];
#pragma unroll
    for (int m = 0; m < 2; m++)
#pragma unroll
        for (int nt = 0; nt < 8; nt++)
#pragma unroll
            for (int v = 0; v < 4; v++) acc[m][nt][v] = 0.0f;

    __syncthreads();   // W staged

#pragma unroll
    for (int q = 0; q < 4; q++) {
        // Load this q's x values: m-tile m, row-halves rr (rows m*16 + rr*8 + r),
        // k-pair halves h -> float2 at col q*16 + 2c + 8h.
        float2 xd[2][2][2];
#pragma unroll
        for (int m = 0; m < 2; m++)
#pragma unroll
            for (int rr = 0; rr < 2; rr++) {
                const float* xrow =
                    x + (size_t)(warp_row0 + m * 16 + rr * 8 + r) * NIN + q * 16 + 2 * c;
                xd[m][rr][0] = *(const float2*)(xrow);
                xd[m][rr][1] = *(const float2*)(xrow + 8);
            }

#pragma unroll
        for (int p = 0; p < 7; p++) {
            uint32_t A[2][4];
#pragma unroll
            for (int m = 0; m < 2; m++)
#pragma unroll
                for (int rr = 0; rr < 2; rr++)
#pragma unroll
                    for (int h = 0; h < 2; h++) {
                        float2 v = xd[m][rr][h];
                        A[m][rr + 2 * h] = pack2(prim_eval(p, v.x), prim_eval(p, v.y));
                    }
            int kk = p * 4 + q;
            const uint2* bp = sW + (kk * 8) * 32 + lane;
#pragma unroll
            for (int nt = 0; nt < 8; nt++) {
                uint2 b = bp[nt * 32];
                mma16816(acc[0][nt], A[0], b);
                mma16816(acc[1][nt], A[1], b);
            }
        }
    }

    // Write out: c0/c1 -> row m*16 + r, c2/c3 -> row m*16 + 8 + r, cols nt*8+2c
#pragma unroll
    for (int m = 0; m < 2; m++) {
#pragma unroll
        for (int hr = 0; hr < 2; hr++) {
            float* orow = out + (size_t)(warp_row0 + m * 16 + hr * 8 + r) * NOUT;
#pragma unroll
            for (int nt = 0; nt < 8; nt++) {
                float2 v;
                v.x = acc[m][nt][hr * 2 + 0];
                v.y = acc[m][nt][hr * 2 + 1];
                *(float2*)(orow + nt * 8 + 2 * c) = v;
            }
        }
    }
}

// --------------------------- launch ------------------------------------------

extern "C" void kernel_launch(void* const* d_in, const int* in_sizes, int n_in,
                              void* d_out, int out_size) {
    (void)in_sizes; (void)n_in; (void)out_size;
    const float* x      = (const float*)d_in[0];
    const float* alphas = (const float*)d_in[1];
    const float* coeffs = (const float*)d_in[2];

    darts_prep_kernel<<<32, 128>>>(alphas, coeffs);

    cudaFuncSetAttribute(darts_main_kernel,
                         cudaFuncAttributeMaxDynamicSharedMemorySize, SMEM_B);
    darts_main_kernel<<<BATCH / 256, 256, SMEM_B>>>(x, (float*)d_out);
}

// round 10
// speedup vs baseline: 1.0101x; 1.0101x over previous
#include <cuda_runtime.h>
#include <cuda_fp16.h>
#include <cstdint>

// ---------------------------------------------------------------------------
// DARTSLayer as one fp16 tensor-core GEMM (mma.sync.m16n8k16):
//   out[b,j] = sum_{p,i} W[p*64+i, j] * prim_p(x[b,i])
// R5 -> R6: W repacked so one LDS.128 loads B-fragments for TWO n-tiles
// (224 LDS.64 -> 112 LDS.128 per warp) to cut MIO pressure; loads hoisted
// per (q,p) block for clean overlap with primitive computation.
// ---------------------------------------------------------------------------

#define BATCH   65536
#define NIN     64
#define NOUT    64
#define NKK     28                // K=448 / 16 per mma
#define WQUAD_N (NKK * 4 * 32)    // kk * ntpair * lane -> uint4 {nt0.b0,nt0.b1,nt1.b0,nt1.b1}
#define SMEM_B  (WQUAD_N * 16)    // 57344 bytes

__device__ uint4 g_Wfrag[WQUAD_N];

// --------------------------- helpers ----------------------------------------

__device__ __forceinline__ uint32_t pack2(float lo, float hi) {
    uint32_t r;
    asm("cvt.rn.f16x2.f32 %0, %1, %2;" : "=r"(r) : "f"(hi), "f"(lo));
    return r;
}

__device__ __forceinline__ float frcp(float x) {
    float r;
    asm("rcp.approx.f32 %0, %1;" : "=f"(r) : "f"(x));
    return r;
}

__device__ __forceinline__ void mma16816(float* d, const uint32_t* a,
                                         uint32_t b0, uint32_t b1) {
    asm volatile(
        "mma.sync.aligned.m16n8k16.row.col.f32.f16.f16.f32 "
        "{%0,%1,%2,%3}, {%4,%5,%6,%7}, {%8,%9}, {%0,%1,%2,%3};"
        : "+f"(d[0]), "+f"(d[1]), "+f"(d[2]), "+f"(d[3])
        : "r"(a[0]), "r"(a[1]), "r"(a[2]), "r"(a[3]), "r"(b0), "r"(b1));
}

__device__ __forceinline__ float prim_eval(int p, float x) {
    switch (p) {
        case 0:  return x;            // linear
        case 1:  return x * x;        // power_two
        case 2:  return x * x * x;    // power_three
        case 3:  return __expf(x);    // exp
        case 4:  return __logf(x);    // ln
        case 5:  return frcp(x);      // reciprocal
        default: return __sinf(x);    // sin
    }
}

// --------------------------- W preparation -----------------------------------
// One thread per (i, j). Scatters softmax-gated weights as fp16 halves into
// the paired B-fragment layout:
//   uint4 element = (kk*4 + ntp)*32 + lane
//   word w = (nt&1)*2 + reg, half h: reg0 holds k=2c,2c+1; reg1 k=2c+8,2c+9
//   n = (lane/4) + 8*nt, c = lane%4, nt = 2*ntp + (nt&1)

__global__ void darts_prep_kernel(const float* __restrict__ alphas,
                                  const float* __restrict__ coeffs) {
    int idx = blockIdx.x * blockDim.x + threadIdx.x;  // i*64 + j
    if (idx >= NIN * NOUT) return;
    int i = idx >> 6;
    int j = idx & 63;

    float a[8];
#pragma unroll
    for (int k = 0; k < 8; k++) a[k] = alphas[idx * 8 + k];
    float m = a[0];
#pragma unroll
    for (int k = 1; k < 8; k++) m = fmaxf(m, a[k]);
    float e[8], s = 0.0f;
#pragma unroll
    for (int k = 0; k < 8; k++) { e[k] = __expf(a[k] - m); s += e[k]; }
    float inv = 1.0f / s;

    __half* dst = (__half*)g_Wfrag;
#pragma unroll
    for (int p = 0; p < 7; p++) {
        float wv = e[p + 1] * inv * coeffs[idx * 8 + p + 1];
        int k    = p * 64 + i;
        int kk   = k >> 4;
        int kpos = k & 15;
        int nt   = j >> 3;
        int ntp  = nt >> 1;
        int lane = (j & 7) * 4 + ((kpos & 7) >> 1);
        int reg  = kpos >> 3;
        int half = kpos & 1;
        int word = (nt & 1) * 2 + reg;
        dst[((((kk * 4 + ntp) * 32 + lane) * 4) + word) * 2 + half] = __float2half_rn(wv);
    }
}

// --------------------------- main GEMM ---------------------------------------
// 256 threads (8 warps). Each warp: 32 batch rows x all 64 outputs x K=448.
// q (i-quarter) outer so only one q's x values (16 regs) are live at a time.
// grid = 256 CTAs (256-row tile each), 2 CTAs/SM.

__global__ void __launch_bounds__(256, 2)
darts_main_kernel(const float* __restrict__ x, float* __restrict__ out) {
    extern __shared__ uint4 sW[];
    int tid  = threadIdx.x;
    int wid  = tid >> 5;
    int lane = tid & 31;
    int r    = lane >> 2;   // 0..7
    int c    = lane & 3;    // 0..3

    // Stage W fragments into SMEM (coalesced uint4 copy, 57344 B)
    {
        const uint4* src = (const uint4*)g_Wfrag;
        for (int u = tid; u < WQUAD_N; u += 256) sW[u] = src[u];
    }

    int warp_row0 = blockIdx.x * 256 + wid * 32;

    float acc[2][8][4];
#pragma unroll
    for (int m = 0; m < 2; m++)
#pragma unroll
        for (int nt = 0; nt < 8; nt++)
#pragma unroll
            for (int v = 0; v < 4; v++) acc[m][nt][v] = 0.0f;

    __syncthreads();   // W staged

#pragma unroll
    for (int q = 0; q < 4; q++) {
        // Load this q's x values: m-tile m, row-halves rr (rows m*16 + rr*8 + r),
        // k-pair halves h -> float2 at col q*16 + 2c + 8h.
        float2 xd[2][2][2];
#pragma unroll
        for (int m = 0; m < 2; m++)
#pragma unroll
            for (int rr = 0; rr < 2; rr++) {
                const float* xrow =
                    x + (size_t)(warp_row0 + m * 16 + rr * 8 + r) * NIN + q * 16 + 2 * c;
                xd[m][rr][0] = *(const float2*)(xrow);
                xd[m][rr][1] = *(const float2*)(xrow + 8);
            }

#pragma unroll
        for (int p = 0; p < 7; p++) {
            int kk = p * 4 + q;
            const uint4* bp = sW + (kk * 4) * 32 + lane;

            // Hoisted B loads: 4 x LDS.128, each = fragments for 2 n-tiles
            uint4 b[4];
#pragma unroll
            for (int ntp = 0; ntp < 4; ntp++) b[ntp] = bp[ntp * 32];

            // Build A fragments (prims of this q's 16 x-values per m-tile)
            uint32_t A[2][4];
#pragma unroll
            for (int m = 0; m < 2; m++)
#pragma unroll
                for (int rr = 0; rr < 2; rr++)
#pragma unroll
                    for (int h = 0; h < 2; h++) {
                        float2 v = xd[m][rr][h];
                        A[m][rr + 2 * h] = pack2(prim_eval(p, v.x), prim_eval(p, v.y));
                    }

#pragma unroll
            for (int ntp = 0; ntp < 4; ntp++) {
                mma16816(acc[0][2 * ntp + 0], A[0], b[ntp].x, b[ntp].y);
                mma16816(acc[1][2 * ntp + 0], A[1], b[ntp].x, b[ntp].y);
                mma16816(acc[0][2 * ntp + 1], A[0], b[ntp].z, b[ntp].w);
                mma16816(acc[1][2 * ntp + 1], A[1], b[ntp].z, b[ntp].w);
            }
        }
    }

    // Write out: c0/c1 -> row m*16 + r, c2/c3 -> row m*16 + 8 + r, cols nt*8+2c
#pragma unroll
    for (int m = 0; m < 2; m++) {
#pragma unroll
        for (int hr = 0; hr < 2; hr++) {
            float* orow = out + (size_t)(warp_row0 + m * 16 + hr * 8 + r) * NOUT;
#pragma unroll
            for (int nt = 0; nt < 8; nt++) {
                float2 v;
                v.x = acc[m][nt][hr * 2 + 0];
                v.y = acc[m][nt][hr * 2 + 1];
                *(float2*)(orow + nt * 8 + 2 * c) = v;
            }
        }
    }
}

// --------------------------- launch ------------------------------------------

extern "C" void kernel_launch(void* const* d_in, const int* in_sizes, int n_in,
                              void* d_out, int out_size) {
    (void)in_sizes; (void)n_in; (void)out_size;
    const float* x      = (const float*)d_in[0];
    const float* alphas = (const float*)d_in[1];
    const float* coeffs = (const float*)d_in[2];

    darts_prep_kernel<<<32, 128>>>(alphas, coeffs);

    cudaFuncSetAttribute(darts_main_kernel,
                         cudaFuncAttributeMaxDynamicSharedMemorySize, SMEM_B);
    darts_main_kernel<<<BATCH / 256, 256, SMEM_B>>>(x, (float*)d_out);
}